// round 13
// baseline (speedup 1.0000x reference)
#include <cuda_runtime.h>
#include <cuda_bf16.h>
#include <cstdint>
#include <math.h>

// Problem constants
#define BB   2
#define SS   2048
#define HH   2048
#define NHH  16
#define HDD  128
#define SCALE 0.08838834764831845f   // 1/sqrt(128)

#if defined(__CUDA_ARCH__) && defined(__CUDA_ARCH_FEAT_SM103_ALL)
#define HAS_TC 1
#else
#define HAS_TC 0
#endif

// ---------------------------------------------------------------------------
// Scratch (device globals)
// ---------------------------------------------------------------------------
__device__ __nv_bfloat16 gq_h[8388608], gq_l[8388608];
__device__ __nv_bfloat16 gk_h[8388608], gk_l[8388608];
__device__ __nv_bfloat16 gv_h[8388608], gv_l[8388608];

__device__ __nv_bfloat16 g_xh[8388608],   g_xl[8388608];
__device__ __nv_bfloat16 g_wqh[12582912], g_wql[12582912];
__device__ __nv_bfloat16 g_ch[8388608],   g_cl[8388608];
__device__ __nv_bfloat16 g_wo[4194304],   g_wol[4194304];

// ---------------------------------------------------------------------------
// PTX helpers
// ---------------------------------------------------------------------------
__device__ __forceinline__ uint32_t smem_to_u32(const void* p) {
    uint32_t a;
    asm("{ .reg .u64 t; cvta.to.shared.u64 t, %1; cvt.u32.u64 %0, t; }"
        : "=r"(a) : "l"(p));
    return a;
}
__device__ __forceinline__ uint32_t elect_one_pred() {
    uint32_t pred;
    asm volatile("{\n\t.reg .pred p;\n\telect.sync _|p, 0xFFFFFFFF;\n\t"
                 "selp.b32 %0, 1, 0, p;\n\t}" : "=r"(pred));
    return pred;
}
#define MBARRIER_INIT(addr, cnt) \
    asm volatile("mbarrier.init.shared.b64 [%0], %1;" :: "r"((uint32_t)(addr)), "r"((uint32_t)(cnt)) : "memory")
#define MBARRIER_WAIT_PARITY(addr, par) do {                                   \
    uint32_t _m = (uint32_t)(addr); uint32_t _p = (uint32_t)(par); uint32_t _d;\
    asm volatile("{\n\t.reg .pred p;\n\t"                                      \
        "mbarrier.try_wait.parity.acquire.cta.shared::cta.b64 p, [%1], %2;\n\t"\
        "selp.b32 %0, 1, 0, p;\n\t}" : "=r"(_d) : "r"(_m), "r"(_p) : "memory");\
    if (!_d) {                                                                 \
        asm volatile("{\n\t.reg .pred P1;\n\t"                                 \
        "WL_%=:\n\t"                                                           \
        "mbarrier.try_wait.parity.acquire.cta.shared::cta.b64 P1, [%0], %1, 0x989680;\n\t" \
        "@P1 bra.uni WD_%=;\n\tbra.uni WL_%=;\n\tWD_%=:\n\t}"                  \
        :: "r"(_m), "r"(_p) : "memory");                                       \
    }                                                                          \
} while (0)
#define TCGEN05_ALLOC(saddr, ncols) \
    asm volatile("tcgen05.alloc.cta_group::1.sync.aligned.shared::cta.b32 [%0], %1;" \
                 :: "r"((uint32_t)(saddr)), "r"((uint32_t)(ncols)) : "memory")
#define TCGEN05_DEALLOC(taddr, ncols) \
    asm volatile("tcgen05.dealloc.cta_group::1.sync.aligned.b32 %0, %1;" :: "r"(taddr), "r"((uint32_t)(ncols)))
#define TCGEN05_RELINQUISH() \
    asm volatile("tcgen05.relinquish_alloc_permit.cta_group::1.sync.aligned;")
#define TCGEN05_COMMIT(mbar) \
    asm volatile("tcgen05.commit.cta_group::1.mbarrier::arrive::one.shared::cluster.b64 [%0];" \
                 :: "r"((uint32_t)(mbar)) : "memory")
#define TCGEN05_WAIT_LD() asm volatile("tcgen05.wait::ld.sync.aligned;" ::: "memory")
#define TCGEN05_FENCE_BEFORE() asm volatile("tcgen05.fence::before_thread_sync;" ::: "memory")
#define TCGEN05_FENCE_AFTER()  asm volatile("tcgen05.fence::after_thread_sync;" ::: "memory")
#define FENCE_PROXY_ASYNC() asm volatile("fence.proxy.async.shared::cta;" ::: "memory")
#define CP_ASYNC16(dst, src) \
    asm volatile("cp.async.cg.shared.global [%0], [%1], 16;" :: "r"((uint32_t)(dst)), "l"(src) : "memory")
#define CP_COMMIT() asm volatile("cp.async.commit_group;" ::: "memory")
#define CP_WAIT_GROUP(n) asm volatile("cp.async.wait_group %0;" :: "n"(n) : "memory")
#define TCGEN05_LD_X32(r, taddr)                                               \
    asm volatile("tcgen05.ld.sync.aligned.32x32b.x32.b32 "                     \
        "{%0, %1, %2, %3, %4, %5, %6, %7, "                                    \
        " %8, %9, %10, %11, %12, %13, %14, %15, "                              \
        " %16, %17, %18, %19, %20, %21, %22, %23, "                            \
        " %24, %25, %26, %27, %28, %29, %30, %31}, [%32];"                     \
        : "=r"((r)[0]), "=r"((r)[1]), "=r"((r)[2]), "=r"((r)[3]),              \
          "=r"((r)[4]), "=r"((r)[5]), "=r"((r)[6]), "=r"((r)[7]),              \
          "=r"((r)[8]), "=r"((r)[9]), "=r"((r)[10]), "=r"((r)[11]),            \
          "=r"((r)[12]), "=r"((r)[13]), "=r"((r)[14]), "=r"((r)[15]),          \
          "=r"((r)[16]), "=r"((r)[17]), "=r"((r)[18]), "=r"((r)[19]),          \
          "=r"((r)[20]), "=r"((r)[21]), "=r"((r)[22]), "=r"((r)[23]),          \
          "=r"((r)[24]), "=r"((r)[25]), "=r"((r)[26]), "=r"((r)[27]),          \
          "=r"((r)[28]), "=r"((r)[29]), "=r"((r)[30]), "=r"((r)[31])           \
        : "r"(taddr))
#define TCGEN05_LD_X16(r, taddr)                                               \
    asm volatile("tcgen05.ld.sync.aligned.32x32b.x16.b32 "                     \
        "{%0, %1, %2, %3, %4, %5, %6, %7, "                                    \
        " %8, %9, %10, %11, %12, %13, %14, %15}, [%16];"                       \
        : "=r"((r)[0]), "=r"((r)[1]), "=r"((r)[2]), "=r"((r)[3]),              \
          "=r"((r)[4]), "=r"((r)[5]), "=r"((r)[6]), "=r"((r)[7]),              \
          "=r"((r)[8]), "=r"((r)[9]), "=r"((r)[10]), "=r"((r)[11]),            \
          "=r"((r)[12]), "=r"((r)[13]), "=r"((r)[14]), "=r"((r)[15])           \
        : "r"(taddr))

#define SMEM_SWIZZLE_128B(b) ((b) ^ (((b) >> 3) & 0x70))
static constexpr uint64_t SMEM_DESC_BASE_SW128 =
    (uint64_t(2) << 61) | (uint64_t(1) << 46) | (uint64_t(64) << 32) | (uint64_t(1) << 16);
#define MAKE_SMEM_DESC(a) (SMEM_DESC_BASE_SW128 | ((uint64_t)((a) >> 4) & 0x3FFF))

#if HAS_TC
__device__ __forceinline__ void mma_ss_f16(uint32_t d, uint64_t a, uint64_t b,
                                           uint32_t idesc, bool acc) {
    uint32_t e = acc ? 1u : 0u;
    asm volatile(
        "{\n\t.reg .pred p;\n\t"
        "setp.ne.u32 p, %5, 0;\n\t"
        "tcgen05.mma.cta_group::1.kind::f16 [%0], %1, %2, %3, {%4, %4, %4, %4}, p;\n\t}"
        :: "r"(d), "l"(a), "l"(b), "r"(idesc), "r"(0u), "r"(e) : "memory");
}
#endif

__device__ __forceinline__ void bf16_split(float v, __nv_bfloat16& h, __nv_bfloat16& l) {
    h = __float2bfloat16_rn(v);
    l = __float2bfloat16_rn(v - __bfloat162float(h));
}

// ---------------------------------------------------------------------------
// Merged split kernel (round-12 passing version)
// ---------------------------------------------------------------------------
__global__ __launch_bounds__(256)
void split_all_kernel(const float* __restrict__ x,
                      const float* __restrict__ wq,
                      const float* __restrict__ wo)
{
    int bid = blockIdx.x;
    const float* s;
    __nv_bfloat16 *hi, *lo;
    int base;
    if (bid < 8192)        { s = x;  hi = g_xh;  lo = g_xl;  base = bid; }
    else if (bid < 20480)  { s = wq; hi = g_wqh; lo = g_wql; base = bid - 8192; }
    else                   { s = wo; hi = g_wo;  lo = g_wol; base = bid - 20480; }

    int i = (base * 256 + threadIdx.x) * 4;
    float4 v = *(const float4*)(s + i);
    __nv_bfloat16 h0, h1, h2, h3, l0, l1, l2, l3;
    bf16_split(v.x, h0, l0); bf16_split(v.y, h1, l1);
    bf16_split(v.z, h2, l2); bf16_split(v.w, h3, l3);
    __nv_bfloat162* H = (__nv_bfloat162*)(hi + i);
    __nv_bfloat162* L = (__nv_bfloat162*)(lo + i);
    H[0] = __halves2bfloat162(h0, h1); H[1] = __halves2bfloat162(h2, h3);
    L[0] = __halves2bfloat162(l0, l1); L[1] = __halves2bfloat162(l2, l3);
}

// ---------------------------------------------------------------------------
// tcgen05 bf16x3 GEMM — 2-stage, BK=32, 2 CTAs/SM, chunk loop UNROLLED x2:
// one CP_WAIT+sync per 2 chunks, both stages' MMAs queued back-to-back
// (2-chunk-deep tensor queue), refills gated on each chunk's own mbarrier.
// ---------------------------------------------------------------------------
#define GBM 128
#define GBN 256
#define GBK 32
#define STAGE_BYTES 49152
#define GEMM_SMEM   (1024 + 2 * STAGE_BYTES)   // 99,328
#define GIDESC ((1u<<4) | (1u<<7) | (1u<<10) | ((GBN/8u)<<17) | ((GBM/16u)<<24))

#if HAS_TC
__device__ __forceinline__ void fill_stage_async(
    uint32_t su, int st,
    const __nv_bfloat16* __restrict__ Ah, const __nv_bfloat16* __restrict__ Al,
    const __nv_bfloat16* __restrict__ Bh, const __nv_bfloat16* __restrict__ Bl,
    int m0, int n0, int k0, int K, int tid)
{
    uint32_t stage = su + 1024 + st * STAGE_BYTES;
#pragma unroll
    for (int i = 0; i < 4; i++) {                 // A: 128 rows
        int q = tid + i * 256;
        int r = q >> 3, c = q & 7;
        uint32_t off = SMEM_SWIZZLE_128B((uint32_t)(r * 128 + c * 16));
        const __nv_bfloat16* srcp = (c < 4)
            ? Ah + (size_t)(m0 + r) * K + k0 + c * 8
            : Al + (size_t)(m0 + r) * K + k0 + (c - 4) * 8;
        CP_ASYNC16(stage + off, srcp);
    }
#pragma unroll
    for (int i = 0; i < 8; i++) {                 // B: 256 rows
        int q = tid + i * 256;
        int r = q >> 3, c = q & 7;
        uint32_t off = SMEM_SWIZZLE_128B((uint32_t)(r * 128 + c * 16));
        const __nv_bfloat16* srcp = (c < 4)
            ? Bh + (size_t)(n0 + r) * K + k0 + c * 8
            : Bl + (size_t)(n0 + r) * K + k0 + (c - 4) * 8;
        CP_ASYNC16(stage + 16384 + off, srcp);
    }
    CP_COMMIT();
}
__device__ __forceinline__ void gemm_issue_chunk(uint32_t su, uint32_t tmem,
                                                 int st, bool acc_first)
{
    uint32_t sb = su + 1024 + st * STAGE_BYTES;
    uint64_t dA = MAKE_SMEM_DESC(sb);
    uint64_t dB = MAKE_SMEM_DESC(sb + 16384);
    mma_ss_f16(tmem, dA + 0, dB + 0, GIDESC, acc_first);
    mma_ss_f16(tmem, dA + 2, dB + 2, GIDESC, true);
    mma_ss_f16(tmem, dA + 0, dB + 4, GIDESC, true);
    mma_ss_f16(tmem, dA + 2, dB + 6, GIDESC, true);
    mma_ss_f16(tmem, dA + 4, dB + 0, GIDESC, true);
    mma_ss_f16(tmem, dA + 6, dB + 2, GIDESC, true);
    TCGEN05_COMMIT(su + st * 8);
}
#endif

template <int MODE>
__global__ __launch_bounds__(256, 2)
void mma_gemm_kernel(const float* __restrict__ bias,
                     float* __restrict__ Cout,
                     int K, int Ntot)
{
#if HAS_TC
    extern __shared__ char sm[];
    const uint32_t su = smem_to_u32(sm);
    const int tid = threadIdx.x;
    const int wid = tid >> 5;
    const int lane = tid & 31;
    const int m0 = blockIdx.y * GBM;
    const int n0 = blockIdx.x * GBN;

    const __nv_bfloat16* Ah = (MODE == 0) ? g_xh  : g_ch;
    const __nv_bfloat16* Al = (MODE == 0) ? g_xl  : g_cl;
    const __nv_bfloat16* Bh = (MODE == 0) ? g_wqh : g_wo;
    const __nv_bfloat16* Bl = (MODE == 0) ? g_wql : g_wol;

    if (tid == 0) { MBARRIER_INIT(su + 0, 1); MBARRIER_INIT(su + 8, 1); }
    if (wid == 0) { TCGEN05_ALLOC(su + 32, 256); TCGEN05_RELINQUISH(); }
    __syncthreads();
    uint32_t tmem;
    asm volatile("ld.shared.b32 %0, [%1];" : "=r"(tmem) : "r"(su + 32));

    const int NC = K / GBK;   // 64 (even)
    fill_stage_async(su, 0, Ah, Al, Bh, Bl, m0, n0, 0 * GBK, K, tid);
    fill_stage_async(su, 1, Ah, Al, Bh, Bl, m0, n0, 1 * GBK, K, tid);

    for (int c = 0; c < NC; c += 2) {
        // fills for chunks c (st0) and c+1 (st1) in flight -> wait both
        CP_WAIT_GROUP(0);
        FENCE_PROXY_ASYNC();
        __syncthreads();

        // queue BOTH chunks' MMAs back-to-back (2-chunk-deep tensor queue)
        if (wid == 0 && elect_one_pred()) {
            gemm_issue_chunk(su, tmem, 0, c != 0);
            gemm_issue_chunk(su, tmem, 1, true);
        }

        // refill stages as their MMAs complete
        if (c + 2 < NC) {
            MBARRIER_WAIT_PARITY(su + 0, (c >> 1) & 1);        // MMA(c) done
            fill_stage_async(su, 0, Ah, Al, Bh, Bl, m0, n0, (c + 2) * GBK, K, tid);
            MBARRIER_WAIT_PARITY(su + 8, (c >> 1) & 1);        // MMA(c+1) done
            fill_stage_async(su, 1, Ah, Al, Bh, Bl, m0, n0, (c + 3) * GBK, K, tid);
        }
    }
    // final chunks' MMAs
    MBARRIER_WAIT_PARITY(su + 0, ((NC - 2) >> 1) & 1);
    MBARRIER_WAIT_PARITY(su + 8, ((NC - 2) >> 1) & 1);
    TCGEN05_FENCE_AFTER();
    __syncthreads();

    float* ep = (float*)(sm + 1024);
    for (int c0 = 0; c0 < GBN; c0 += 32) {
        if (wid < 4) {
            uint32_t regs[32];
            TCGEN05_LD_X32(regs, tmem + c0);
            TCGEN05_WAIT_LD();
            int r = wid * 32 + lane;
#pragma unroll
            for (int c = 0; c < 32; c++) ep[r * 33 + c] = __uint_as_float(regs[c]);
        }
        __syncthreads();
        const int n_base = n0 + c0;
        const int which = n_base >> 11;

        if (MODE == 0 && which == 2) {
            int rest = n_base & 2047;
            int h = rest >> 7, dbase = rest & 127;
            size_t head = (size_t)((m0 >> 11) * NHH + h);
            int s0 = m0 & 2047;
#pragma unroll
            for (int k4 = 0; k4 < 4; k4++) {
                int col = wid * 4 + k4;
                float bval = bias[n_base + col];
                __nv_bfloat16* dh = gv_h + (head * HDD + dbase + col) * SS + s0;
                __nv_bfloat16* dl = gv_l + (head * HDD + dbase + col) * SS + s0;
#pragma unroll
                for (int j = 0; j < 4; j++) {
                    int r = lane + j * 32;
                    float val = ep[r * 33 + col] + bval;
                    __nv_bfloat16 hh, ll;
                    bf16_split(val, hh, ll);
                    dh[r] = hh; dl[r] = ll;
                }
            }
        } else {
#pragma unroll
            for (int i = 0; i < 4; i++) {
                int idx = tid + i * 256;
                int r = idx >> 3, q = idx & 7;
                float4 v;
                v.x = ep[r * 33 + q * 4 + 0] + bias[n_base + q * 4 + 0];
                v.y = ep[r * 33 + q * 4 + 1] + bias[n_base + q * 4 + 1];
                v.z = ep[r * 33 + q * 4 + 2] + bias[n_base + q * 4 + 2];
                v.w = ep[r * 33 + q * 4 + 3] + bias[n_base + q * 4 + 3];
                int m = m0 + r;
                if (MODE == 0) {
                    int bb = m >> 11, s = m & 2047;
                    int rest = n_base & 2047;
                    int h = rest >> 7;
                    int d = (rest & 127) + q * 4;
                    size_t off = (((size_t)(bb * NHH + h)) * SS + s) * HDD + d;
                    if (which == 0) { v.x *= SCALE; v.y *= SCALE; v.z *= SCALE; v.w *= SCALE; }
                    __nv_bfloat16 h0, h1, h2, h3, l0, l1, l2, l3;
                    bf16_split(v.x, h0, l0); bf16_split(v.y, h1, l1);
                    bf16_split(v.z, h2, l2); bf16_split(v.w, h3, l3);
                    __nv_bfloat16* dh = (which == 0) ? gq_h : gk_h;
                    __nv_bfloat16* dl = (which == 0) ? gq_l : gk_l;
                    ((__nv_bfloat162*)(dh + off))[0] = __halves2bfloat162(h0, h1);
                    ((__nv_bfloat162*)(dh + off))[1] = __halves2bfloat162(h2, h3);
                    ((__nv_bfloat162*)(dl + off))[0] = __halves2bfloat162(l0, l1);
                    ((__nv_bfloat162*)(dl + off))[1] = __halves2bfloat162(l2, l3);
                } else {
                    *(float4*)(Cout + (size_t)m * Ntot + n_base + q * 4) = v;
                }
            }
        }
        __syncthreads();
    }
    if (wid == 0) TCGEN05_DEALLOC(tmem, 256);
#endif
}

// ---------------------------------------------------------------------------
// Causal flash attention (round-12 passing version, UNCHANGED):
// 512 threads, no-rescale softmax, persistent TMEM accumulator.
// ---------------------------------------------------------------------------
#define FLT  512
#define FL_Q    1024
#define FL_K    (FL_Q + 65536)
#define FL_V    (FL_K + 65536)
#define FL_P    (FL_V + 65536)
#define FL_RED  (FL_P + 32768)
#define FL_SMEM (FL_RED + 2048)
#define FIDESC_QK ((1u<<4) | (1u<<7) | (1u<<10) | (8u<<17)  | (8u<<24))   // N=64
#define FIDESC_PV ((1u<<4) | (1u<<7) | (1u<<10) | (16u<<17) | (8u<<24))   // N=128

#if HAS_TC
__device__ __forceinline__ void flash_fill_k(
    uint32_t su, const __nv_bfloat16* Kh, const __nv_bfloat16* Kl,
    int kt, int buf, int tid)
{
    uint32_t base = su + FL_K + buf * 32768;
#pragma unroll
    for (int it = 0; it < 2; it++) {
        int vec = tid + it * FLT;
        int r = vec >> 4;
        int dc = (vec >> 3) & 1;
        int i = vec & 7;
        uint32_t off = dc * 8192 + SMEM_SWIZZLE_128B((uint32_t)(r * 128 + i * 16));
        size_t src = ((size_t)kt * 64 + r) * HDD + dc * 64 + i * 8;
        CP_ASYNC16(base + off,         Kh + src);
        CP_ASYNC16(base + 16384 + off, Kl + src);
    }
    CP_COMMIT();
}
__device__ __forceinline__ void flash_fill_v(
    uint32_t su, const __nv_bfloat16* Vh, const __nv_bfloat16* Vl,
    int kt, int buf, int tid)
{
    uint32_t base = su + FL_V + buf * 32768;
#pragma unroll
    for (int it = 0; it < 2; it++) {
        int vec = tid + it * FLT;
        int d = vec >> 3;
        int i = vec & 7;
        uint32_t off = SMEM_SWIZZLE_128B((uint32_t)(d * 128 + i * 16));
        size_t src = (size_t)d * SS + kt * 64 + i * 8;
        CP_ASYNC16(base + off,         Vh + src);
        CP_ASYNC16(base + 16384 + off, Vl + src);
    }
    CP_COMMIT();
}
__device__ __forceinline__ void flash_issue_qk(uint32_t su, uint32_t tmem,
                                               uint32_t scol, int kbuf)
{
    bool first = true;
#pragma unroll
    for (int p = 0; p < 3; p++) {
        uint32_t ab = su + FL_Q + ((p == 2) ? 32768 : 0);
        uint32_t bb2 = su + FL_K + kbuf * 32768 + ((p == 1) ? 16384 : 0);
#pragma unroll
        for (int dc = 0; dc < 2; dc++) {
            uint64_t a = MAKE_SMEM_DESC(ab + dc * 16384);
            uint64_t b = MAKE_SMEM_DESC(bb2 + dc * 8192);
#pragma unroll
            for (int st = 0; st < 4; st++) {
                mma_ss_f16(tmem + scol, a + st * 2, b + st * 2, FIDESC_QK, !first);
                first = false;
            }
        }
    }
    TCGEN05_COMMIT(su + 16);
}
#endif

__global__ __launch_bounds__(FLT)
void flash_tc_kernel()
{
#if HAS_TC
    extern __shared__ char sm[];
    const uint32_t su = smem_to_u32(sm);
    const int tid = threadIdx.x;
    const int wid = tid >> 5;
    const int lane = tid & 31;
    const int q4 = wid >> 2;
    const int row = (wid & 3) * 32 + lane;
    const int qt = gridDim.x - 1 - blockIdx.x;
    const int bh = blockIdx.y;

    const size_t hoff = (size_t)bh * SS * HDD;
    const __nv_bfloat16 *Qh = gq_h + hoff, *Ql = gq_l + hoff;
    const __nv_bfloat16 *Kh = gk_h + hoff, *Kl = gk_l + hoff;
    const __nv_bfloat16 *Vh = gv_h + hoff, *Vl = gv_l + hoff;

    if (tid == 0) { MBARRIER_INIT(su + 16, 1); MBARRIER_INIT(su + 24, 1); }
    if (wid == 0) { TCGEN05_ALLOC(su + 0, 256); TCGEN05_RELINQUISH(); }
    __syncthreads();
    uint32_t tmem;
    asm volatile("ld.shared.b32 %0, [%1];" : "=r"(tmem) : "r"(su + 0));

    const int KT = 2 * qt + 2;

#pragma unroll
    for (int it = 0; it < 4; it++) {
        int vec = tid + it * FLT;
        int r = vec >> 4;
        int dc = (vec >> 3) & 1;
        int i = vec & 7;
        uint32_t off = dc * 16384 + SMEM_SWIZZLE_128B((uint32_t)(r * 128 + i * 16));
        size_t src = ((size_t)qt * 128 + r) * HDD + dc * 64 + i * 8;
        CP_ASYNC16(su + FL_Q + off,         Qh + src);
        CP_ASYNC16(su + FL_Q + 32768 + off, Ql + src);
    }
    CP_COMMIT();
    flash_fill_k(su, Kh, Kl, 0, 0, tid);
    flash_fill_v(su, Vh, Vl, 0, 0, tid);
    flash_fill_k(su, Kh, Kl, 1 < KT ? 1 : 0, 1, tid);
    flash_fill_v(su, Vh, Vl, 1 < KT ? 1 : 0, 1, tid);

    CP_WAIT_GROUP(2);
    FENCE_PROXY_ASYNC();
    __syncthreads();
    TCGEN05_FENCE_AFTER();
    if (wid == 0 && elect_one_pred()) flash_issue_qk(su, tmem, 0, 0);

    float l_i = 0.0f;
    float* reds = (float*)(sm + FL_RED);
    const int grow = qt * 128 + row;

    for (int kt = 0; kt < KT; kt++) {
        MBARRIER_WAIT_PARITY(su + 16, kt & 1);
        TCGEN05_FENCE_AFTER();

        {
            int kf = kt + 2 < KT ? kt + 2 : KT - 1;
            flash_fill_k(su, Kh, Kl, kf, kt & 1, tid);
        }

        const uint32_t scol = (uint32_t)((kt & 1) * 64);
        uint32_t sreg[16];
        TCGEN05_LD_X16(sreg, tmem + scol + q4 * 16);
        TCGEN05_WAIT_LD();

        const int gc0 = kt * 64 + q4 * 16;
        float sv[16];
        float ps = 0.0f;
#pragma unroll
        for (int c = 0; c < 16; c++) {
            float s = __uint_as_float(sreg[c]);
            float p = (gc0 + c > grow) ? 0.0f : __expf(s);
            sv[c] = p;
            ps += p;
        }
        l_i += ps;
        TCGEN05_FENCE_BEFORE();

        CP_WAIT_GROUP(1);
        FENCE_PROXY_ASYNC();
        __syncthreads();
        TCGEN05_FENCE_AFTER();

        if (kt + 1 < KT && wid == 0 && elect_one_pred())
            flash_issue_qk(su, tmem, (uint32_t)(((kt + 1) & 1) * 64), (kt + 1) & 1);

        if (kt >= 1) {
            MBARRIER_WAIT_PARITY(su + 24, (kt - 1) & 1);
            int vf = kt + 1 < KT ? kt + 1 : KT - 1;
            flash_fill_v(su, Vh, Vl, vf, (kt + 1) & 1, tid);
        }

#pragma unroll
        for (int i = 0; i < 2; i++) {
            uint32_t wh[4], wl[4];
#pragma unroll
            for (int g = 0; g < 4; g++) {
                __nv_bfloat16 h0, l0, h1, l1;
                bf16_split(sv[i * 8 + g * 2 + 0], h0, l0);
                bf16_split(sv[i * 8 + g * 2 + 1], h1, l1);
                __nv_bfloat162 ph = __halves2bfloat162(h0, h1);
                __nv_bfloat162 pl = __halves2bfloat162(l0, l1);
                wh[g] = *(uint32_t*)&ph;
                wl[g] = *(uint32_t*)&pl;
            }
            uint32_t off = SMEM_SWIZZLE_128B((uint32_t)(row * 128 + q4 * 32 + i * 16));
            asm volatile("st.shared.v4.b32 [%0], {%1,%2,%3,%4};"
                :: "r"(su + FL_P + off), "r"(wh[0]), "r"(wh[1]), "r"(wh[2]), "r"(wh[3]) : "memory");
            asm volatile("st.shared.v4.b32 [%0], {%1,%2,%3,%4};"
                :: "r"(su + FL_P + 16384 + off), "r"(wl[0]), "r"(wl[1]), "r"(wl[2]), "r"(wl[3]) : "memory");
        }
        FENCE_PROXY_ASYNC();
        __syncthreads();
        TCGEN05_FENCE_AFTER();

        if (wid == 0) {
            if (elect_one_pred()) {
                uint32_t vbase = su + FL_V + (kt & 1) * 32768;
                bool first = (kt == 0);
#pragma unroll
                for (int p = 0; p < 3; p++) {
                    uint64_t a = MAKE_SMEM_DESC(su + FL_P + ((p == 2) ? 16384 : 0));
                    uint64_t b = MAKE_SMEM_DESC(vbase + ((p == 1) ? 16384 : 0));
#pragma unroll
                    for (int st = 0; st < 4; st++) {
                        mma_ss_f16(tmem + 128, a + st * 2, b + st * 2, FIDESC_PV, !first);
                        first = false;
                    }
                }
                TCGEN05_COMMIT(su + 24);
            }
        }
    }

    MBARRIER_WAIT_PARITY(su + 24, (KT - 1) & 1);
    TCGEN05_FENCE_AFTER();
    reds[q4 * 128 + row] = l_i;
    __syncthreads();
    float l = 0.0f;
#pragma unroll
    for (int j = 0; j < 4; j++) l += reds[j * 128 + row];
    const float inv = 1.0f / l;

    float O[32];
    {
        uint32_t dreg[32];
        TCGEN05_LD_X32(dreg, tmem + 128 + q4 * 32);
        TCGEN05_WAIT_LD();
#pragma unroll
        for (int j = 0; j < 32; j++) O[j] = __uint_as_float(dreg[j]);
    }
    CP_WAIT_GROUP(0);

    const int b = bh >> 4, h = bh & 15;
    const int s = qt * 128 + row;
    size_t base = ((size_t)b * SS + s) * HH + h * HDD + q4 * 32;
    __nv_bfloat162* dh = (__nv_bfloat162*)(g_ch + base);
    __nv_bfloat162* dl = (__nv_bfloat162*)(g_cl + base);
#pragma unroll
    for (int i = 0; i < 16; i++) {
        __nv_bfloat16 h0, l0, h1, l1;
        bf16_split(O[i * 2 + 0] * inv, h0, l0);
        bf16_split(O[i * 2 + 1] * inv, h1, l1);
        dh[i] = __halves2bfloat162(h0, h1);
        dl[i] = __halves2bfloat162(l0, l1);
    }
    TCGEN05_FENCE_BEFORE();
    __syncthreads();
    if (wid == 0) TCGEN05_DEALLOC(tmem, 256);
#endif
}

// ---------------------------------------------------------------------------
// Launch sequence
// ---------------------------------------------------------------------------
extern "C" void kernel_launch(void* const* d_in, const int* in_sizes, int n_in,
                              void* d_out, int out_size)
{
    (void)in_sizes; (void)n_in; (void)out_size;
    const float* x     = (const float*)d_in[0];
    const float* w_qkv = (const float*)d_in[2];
    const float* b_qkv = (const float*)d_in[3];
    const float* w_out = (const float*)d_in[4];
    const float* b_out = (const float*)d_in[5];
    float* out = (float*)d_out;

    cudaFuncSetAttribute(mma_gemm_kernel<0>,
        cudaFuncAttributeMaxDynamicSharedMemorySize, GEMM_SMEM);
    cudaFuncSetAttribute(mma_gemm_kernel<1>,
        cudaFuncAttributeMaxDynamicSharedMemorySize, GEMM_SMEM);
    cudaFuncSetAttribute(flash_tc_kernel,
        cudaFuncAttributeMaxDynamicSharedMemorySize, FL_SMEM);

    // 1) Split fp32 operands into bf16 hi/lo (single launch)
    split_all_kernel<<<24576, 256>>>(x, w_qkv, w_out);

    // 2) QKV projection (unrolled-x2 2-stage GEMM, 2 CTAs/SM)
    {
        dim3 grid(6144 / GBN, 4096 / GBM);
        mma_gemm_kernel<0><<<grid, 256, GEMM_SMEM>>>(b_qkv, nullptr, 2048, 6144);
    }

    // 3) Causal flash attention (512 threads, no-rescale, persistent acc)
    {
        dim3 grid(SS / 128, BB * NHH);
        flash_tc_kernel<<<grid, FLT, FL_SMEM>>>();
    }

    // 4) Output projection
    {
        dim3 grid(2048 / GBN, 4096 / GBM);
        mma_gemm_kernel<1><<<grid, 256, GEMM_SMEM>>>(b_out, out, 2048, 2048);
    }
}

// round 14
// speedup vs baseline: 1.0515x; 1.0515x over previous
#include <cuda_runtime.h>
#include <cuda_bf16.h>
#include <cstdint>
#include <math.h>

// Problem constants
#define BB   2
#define SS   2048
#define HH   2048
#define NHH  16
#define HDD  128
#define SCALE 0.08838834764831845f   // 1/sqrt(128)

#if defined(__CUDA_ARCH__) && defined(__CUDA_ARCH_FEAT_SM103_ALL)
#define HAS_TC 1
#else
#define HAS_TC 0
#endif

// ---------------------------------------------------------------------------
// Scratch (device globals)
// ---------------------------------------------------------------------------
__device__ __nv_bfloat16 gq_h[8388608], gq_l[8388608];
__device__ __nv_bfloat16 gk_h[8388608], gk_l[8388608];
__device__ __nv_bfloat16 gv_h[8388608], gv_l[8388608];

__device__ __nv_bfloat16 g_xh[8388608],   g_xl[8388608];
__device__ __nv_bfloat16 g_wqh[12582912], g_wql[12582912];
__device__ __nv_bfloat16 g_ch[8388608],   g_cl[8388608];
__device__ __nv_bfloat16 g_wo[4194304],   g_wol[4194304];

// ---------------------------------------------------------------------------
// PTX helpers
// ---------------------------------------------------------------------------
__device__ __forceinline__ uint32_t smem_to_u32(const void* p) {
    uint32_t a;
    asm("{ .reg .u64 t; cvta.to.shared.u64 t, %1; cvt.u32.u64 %0, t; }"
        : "=r"(a) : "l"(p));
    return a;
}
__device__ __forceinline__ uint32_t elect_one_pred() {
    uint32_t pred;
    asm volatile("{\n\t.reg .pred p;\n\telect.sync _|p, 0xFFFFFFFF;\n\t"
                 "selp.b32 %0, 1, 0, p;\n\t}" : "=r"(pred));
    return pred;
}
#define MBARRIER_INIT(addr, cnt) \
    asm volatile("mbarrier.init.shared.b64 [%0], %1;" :: "r"((uint32_t)(addr)), "r"((uint32_t)(cnt)) : "memory")
#define MBARRIER_WAIT_PARITY(addr, par) do {                                   \
    uint32_t _m = (uint32_t)(addr); uint32_t _p = (uint32_t)(par); uint32_t _d;\
    asm volatile("{\n\t.reg .pred p;\n\t"                                      \
        "mbarrier.try_wait.parity.acquire.cta.shared::cta.b64 p, [%1], %2;\n\t"\
        "selp.b32 %0, 1, 0, p;\n\t}" : "=r"(_d) : "r"(_m), "r"(_p) : "memory");\
    if (!_d) {                                                                 \
        asm volatile("{\n\t.reg .pred P1;\n\t"                                 \
        "WL_%=:\n\t"                                                           \
        "mbarrier.try_wait.parity.acquire.cta.shared::cta.b64 P1, [%0], %1, 0x989680;\n\t" \
        "@P1 bra.uni WD_%=;\n\tbra.uni WL_%=;\n\tWD_%=:\n\t}"                  \
        :: "r"(_m), "r"(_p) : "memory");                                       \
    }                                                                          \
} while (0)
#define TCGEN05_ALLOC(saddr, ncols) \
    asm volatile("tcgen05.alloc.cta_group::1.sync.aligned.shared::cta.b32 [%0], %1;" \
                 :: "r"((uint32_t)(saddr)), "r"((uint32_t)(ncols)) : "memory")
#define TCGEN05_DEALLOC(taddr, ncols) \
    asm volatile("tcgen05.dealloc.cta_group::1.sync.aligned.b32 %0, %1;" :: "r"(taddr), "r"((uint32_t)(ncols)))
#define TCGEN05_RELINQUISH() \
    asm volatile("tcgen05.relinquish_alloc_permit.cta_group::1.sync.aligned;")
#define TCGEN05_COMMIT(mbar) \
    asm volatile("tcgen05.commit.cta_group::1.mbarrier::arrive::one.shared::cluster.b64 [%0];" \
                 :: "r"((uint32_t)(mbar)) : "memory")
#define TCGEN05_WAIT_LD() asm volatile("tcgen05.wait::ld.sync.aligned;" ::: "memory")
#define TCGEN05_FENCE_BEFORE() asm volatile("tcgen05.fence::before_thread_sync;" ::: "memory")
#define TCGEN05_FENCE_AFTER()  asm volatile("tcgen05.fence::after_thread_sync;" ::: "memory")
#define FENCE_PROXY_ASYNC() asm volatile("fence.proxy.async.shared::cta;" ::: "memory")
#define CP_ASYNC16(dst, src) \
    asm volatile("cp.async.cg.shared.global [%0], [%1], 16;" :: "r"((uint32_t)(dst)), "l"(src) : "memory")
#define CP_COMMIT() asm volatile("cp.async.commit_group;" ::: "memory")
#define CP_WAIT_GROUP(n) asm volatile("cp.async.wait_group %0;" :: "n"(n) : "memory")
#define TCGEN05_LD_X32(r, taddr)                                               \
    asm volatile("tcgen05.ld.sync.aligned.32x32b.x32.b32 "                     \
        "{%0, %1, %2, %3, %4, %5, %6, %7, "                                    \
        " %8, %9, %10, %11, %12, %13, %14, %15, "                              \
        " %16, %17, %18, %19, %20, %21, %22, %23, "                            \
        " %24, %25, %26, %27, %28, %29, %30, %31}, [%32];"                     \
        : "=r"((r)[0]), "=r"((r)[1]), "=r"((r)[2]), "=r"((r)[3]),              \
          "=r"((r)[4]), "=r"((r)[5]), "=r"((r)[6]), "=r"((r)[7]),              \
          "=r"((r)[8]), "=r"((r)[9]), "=r"((r)[10]), "=r"((r)[11]),            \
          "=r"((r)[12]), "=r"((r)[13]), "=r"((r)[14]), "=r"((r)[15]),          \
          "=r"((r)[16]), "=r"((r)[17]), "=r"((r)[18]), "=r"((r)[19]),          \
          "=r"((r)[20]), "=r"((r)[21]), "=r"((r)[22]), "=r"((r)[23]),          \
          "=r"((r)[24]), "=r"((r)[25]), "=r"((r)[26]), "=r"((r)[27]),          \
          "=r"((r)[28]), "=r"((r)[29]), "=r"((r)[30]), "=r"((r)[31])           \
        : "r"(taddr))
#define TCGEN05_LD_X16(r, taddr)                                               \
    asm volatile("tcgen05.ld.sync.aligned.32x32b.x16.b32 "                     \
        "{%0, %1, %2, %3, %4, %5, %6, %7, "                                    \
        " %8, %9, %10, %11, %12, %13, %14, %15}, [%16];"                       \
        : "=r"((r)[0]), "=r"((r)[1]), "=r"((r)[2]), "=r"((r)[3]),              \
          "=r"((r)[4]), "=r"((r)[5]), "=r"((r)[6]), "=r"((r)[7]),              \
          "=r"((r)[8]), "=r"((r)[9]), "=r"((r)[10]), "=r"((r)[11]),            \
          "=r"((r)[12]), "=r"((r)[13]), "=r"((r)[14]), "=r"((r)[15])           \
        : "r"(taddr))

#define SMEM_SWIZZLE_128B(b) ((b) ^ (((b) >> 3) & 0x70))
static constexpr uint64_t SMEM_DESC_BASE_SW128 =
    (uint64_t(2) << 61) | (uint64_t(1) << 46) | (uint64_t(64) << 32) | (uint64_t(1) << 16);
#define MAKE_SMEM_DESC(a) (SMEM_DESC_BASE_SW128 | ((uint64_t)((a) >> 4) & 0x3FFF))

#if HAS_TC
__device__ __forceinline__ void mma_ss_f16(uint32_t d, uint64_t a, uint64_t b,
                                           uint32_t idesc, bool acc) {
    uint32_t e = acc ? 1u : 0u;
    asm volatile(
        "{\n\t.reg .pred p;\n\t"
        "setp.ne.u32 p, %5, 0;\n\t"
        "tcgen05.mma.cta_group::1.kind::f16 [%0], %1, %2, %3, {%4, %4, %4, %4}, p;\n\t}"
        :: "r"(d), "l"(a), "l"(b), "r"(idesc), "r"(0u), "r"(e) : "memory");
}
#endif

__device__ __forceinline__ void bf16_split(float v, __nv_bfloat16& h, __nv_bfloat16& l) {
    h = __float2bfloat16_rn(v);
    l = __float2bfloat16_rn(v - __bfloat162float(h));
}

// ---------------------------------------------------------------------------
// Merged split kernel (round-12 passing version)
// ---------------------------------------------------------------------------
__global__ __launch_bounds__(256)
void split_all_kernel(const float* __restrict__ x,
                      const float* __restrict__ wq,
                      const float* __restrict__ wo)
{
    int bid = blockIdx.x;
    const float* s;
    __nv_bfloat16 *hi, *lo;
    int base;
    if (bid < 8192)        { s = x;  hi = g_xh;  lo = g_xl;  base = bid; }
    else if (bid < 20480)  { s = wq; hi = g_wqh; lo = g_wql; base = bid - 8192; }
    else                   { s = wo; hi = g_wo;  lo = g_wol; base = bid - 20480; }

    int i = (base * 256 + threadIdx.x) * 4;
    float4 v = *(const float4*)(s + i);
    __nv_bfloat16 h0, h1, h2, h3, l0, l1, l2, l3;
    bf16_split(v.x, h0, l0); bf16_split(v.y, h1, l1);
    bf16_split(v.z, h2, l2); bf16_split(v.w, h3, l3);
    __nv_bfloat162* H = (__nv_bfloat162*)(hi + i);
    __nv_bfloat162* L = (__nv_bfloat162*)(lo + i);
    H[0] = __halves2bfloat162(h0, h1); H[1] = __halves2bfloat162(h2, h3);
    L[0] = __halves2bfloat162(l0, l1); L[1] = __halves2bfloat162(l2, l3);
}

// ---------------------------------------------------------------------------
// tcgen05 bf16x3 GEMM — EXACT round-12/7 version (2-stage, BK=32, 2 CTAs/SM,
// per-chunk loop). Do not restructure: proven local optimum.
// ---------------------------------------------------------------------------
#define GBM 128
#define GBN 256
#define GBK 32
#define STAGE_BYTES 49152
#define GEMM_SMEM   (1024 + 2 * STAGE_BYTES)   // 99,328
#define GIDESC ((1u<<4) | (1u<<7) | (1u<<10) | ((GBN/8u)<<17) | ((GBM/16u)<<24))

#if HAS_TC
__device__ __forceinline__ void fill_stage_async(
    uint32_t su, int st,
    const __nv_bfloat16* __restrict__ Ah, const __nv_bfloat16* __restrict__ Al,
    const __nv_bfloat16* __restrict__ Bh, const __nv_bfloat16* __restrict__ Bl,
    int m0, int n0, int k0, int K, int tid)
{
    uint32_t stage = su + 1024 + st * STAGE_BYTES;
#pragma unroll
    for (int i = 0; i < 4; i++) {                 // A: 128 rows
        int q = tid + i * 256;
        int r = q >> 3, c = q & 7;
        uint32_t off = SMEM_SWIZZLE_128B((uint32_t)(r * 128 + c * 16));
        const __nv_bfloat16* srcp = (c < 4)
            ? Ah + (size_t)(m0 + r) * K + k0 + c * 8
            : Al + (size_t)(m0 + r) * K + k0 + (c - 4) * 8;
        CP_ASYNC16(stage + off, srcp);
    }
#pragma unroll
    for (int i = 0; i < 8; i++) {                 // B: 256 rows
        int q = tid + i * 256;
        int r = q >> 3, c = q & 7;
        uint32_t off = SMEM_SWIZZLE_128B((uint32_t)(r * 128 + c * 16));
        const __nv_bfloat16* srcp = (c < 4)
            ? Bh + (size_t)(n0 + r) * K + k0 + c * 8
            : Bl + (size_t)(n0 + r) * K + k0 + (c - 4) * 8;
        CP_ASYNC16(stage + 16384 + off, srcp);
    }
    CP_COMMIT();
}
#endif

template <int MODE>
__global__ __launch_bounds__(256, 2)
void mma_gemm_kernel(const float* __restrict__ bias,
                     float* __restrict__ Cout,
                     int K, int Ntot)
{
#if HAS_TC
    extern __shared__ char sm[];
    const uint32_t su = smem_to_u32(sm);
    const int tid = threadIdx.x;
    const int wid = tid >> 5;
    const int lane = tid & 31;
    const int m0 = blockIdx.y * GBM;
    const int n0 = blockIdx.x * GBN;

    const __nv_bfloat16* Ah = (MODE == 0) ? g_xh  : g_ch;
    const __nv_bfloat16* Al = (MODE == 0) ? g_xl  : g_cl;
    const __nv_bfloat16* Bh = (MODE == 0) ? g_wqh : g_wo;
    const __nv_bfloat16* Bl = (MODE == 0) ? g_wql : g_wol;

    if (tid == 0) { MBARRIER_INIT(su + 0, 1); MBARRIER_INIT(su + 8, 1); }
    if (wid == 0) { TCGEN05_ALLOC(su + 32, 256); TCGEN05_RELINQUISH(); }
    __syncthreads();
    uint32_t tmem;
    asm volatile("ld.shared.b32 %0, [%1];" : "=r"(tmem) : "r"(su + 32));

    const int NC = K / GBK;   // 64
    fill_stage_async(su, 0, Ah, Al, Bh, Bl, m0, n0, 0 * GBK, K, tid);
    fill_stage_async(su, 1, Ah, Al, Bh, Bl, m0, n0, 1 * GBK, K, tid);

    for (int c = 0; c < NC; c++) {
        const int st = c & 1;
        if (c < NC - 1) CP_WAIT_GROUP(1);
        else            CP_WAIT_GROUP(0);
        FENCE_PROXY_ASYNC();
        __syncthreads();

        if (wid == 0) {
            if (elect_one_pred()) {
                uint32_t sb = su + 1024 + st * STAGE_BYTES;
                uint64_t dA = MAKE_SMEM_DESC(sb);
                uint64_t dB = MAKE_SMEM_DESC(sb + 16384);
                mma_ss_f16(tmem, dA + 0, dB + 0, GIDESC, c != 0);
                mma_ss_f16(tmem, dA + 2, dB + 2, GIDESC, true);
                mma_ss_f16(tmem, dA + 0, dB + 4, GIDESC, true);
                mma_ss_f16(tmem, dA + 2, dB + 6, GIDESC, true);
                mma_ss_f16(tmem, dA + 4, dB + 0, GIDESC, true);
                mma_ss_f16(tmem, dA + 6, dB + 2, GIDESC, true);
                TCGEN05_COMMIT(su + st * 8);
            }
        }
        if (c + 2 < NC) {
            MBARRIER_WAIT_PARITY(su + st * 8, (c >> 1) & 1);
            fill_stage_async(su, st, Ah, Al, Bh, Bl, m0, n0, (c + 2) * GBK, K, tid);
        }
    }
    MBARRIER_WAIT_PARITY(su + ((NC - 1) & 1) * 8, ((NC - 1) >> 1) & 1);
    TCGEN05_FENCE_AFTER();
    __syncthreads();

    float* ep = (float*)(sm + 1024);
    for (int c0 = 0; c0 < GBN; c0 += 32) {
        if (wid < 4) {
            uint32_t regs[32];
            TCGEN05_LD_X32(regs, tmem + c0);
            TCGEN05_WAIT_LD();
            int r = wid * 32 + lane;
#pragma unroll
            for (int c = 0; c < 32; c++) ep[r * 33 + c] = __uint_as_float(regs[c]);
        }
        __syncthreads();
        const int n_base = n0 + c0;
        const int which = n_base >> 11;

        if (MODE == 0 && which == 2) {
            int rest = n_base & 2047;
            int h = rest >> 7, dbase = rest & 127;
            size_t head = (size_t)((m0 >> 11) * NHH + h);
            int s0 = m0 & 2047;
#pragma unroll
            for (int k4 = 0; k4 < 4; k4++) {
                int col = wid * 4 + k4;
                float bval = bias[n_base + col];
                __nv_bfloat16* dh = gv_h + (head * HDD + dbase + col) * SS + s0;
                __nv_bfloat16* dl = gv_l + (head * HDD + dbase + col) * SS + s0;
#pragma unroll
                for (int j = 0; j < 4; j++) {
                    int r = lane + j * 32;
                    float val = ep[r * 33 + col] + bval;
                    __nv_bfloat16 hh, ll;
                    bf16_split(val, hh, ll);
                    dh[r] = hh; dl[r] = ll;
                }
            }
        } else {
#pragma unroll
            for (int i = 0; i < 4; i++) {
                int idx = tid + i * 256;
                int r = idx >> 3, q = idx & 7;
                float4 v;
                v.x = ep[r * 33 + q * 4 + 0] + bias[n_base + q * 4 + 0];
                v.y = ep[r * 33 + q * 4 + 1] + bias[n_base + q * 4 + 1];
                v.z = ep[r * 33 + q * 4 + 2] + bias[n_base + q * 4 + 2];
                v.w = ep[r * 33 + q * 4 + 3] + bias[n_base + q * 4 + 3];
                int m = m0 + r;
                if (MODE == 0) {
                    int bb = m >> 11, s = m & 2047;
                    int rest = n_base & 2047;
                    int h = rest >> 7;
                    int d = (rest & 127) + q * 4;
                    size_t off = (((size_t)(bb * NHH + h)) * SS + s) * HDD + d;
                    if (which == 0) { v.x *= SCALE; v.y *= SCALE; v.z *= SCALE; v.w *= SCALE; }
                    __nv_bfloat16 h0, h1, h2, h3, l0, l1, l2, l3;
                    bf16_split(v.x, h0, l0); bf16_split(v.y, h1, l1);
                    bf16_split(v.z, h2, l2); bf16_split(v.w, h3, l3);
                    __nv_bfloat16* dh = (which == 0) ? gq_h : gk_h;
                    __nv_bfloat16* dl = (which == 0) ? gq_l : gk_l;
                    ((__nv_bfloat162*)(dh + off))[0] = __halves2bfloat162(h0, h1);
                    ((__nv_bfloat162*)(dh + off))[1] = __halves2bfloat162(h2, h3);
                    ((__nv_bfloat162*)(dl + off))[0] = __halves2bfloat162(l0, l1);
                    ((__nv_bfloat162*)(dl + off))[1] = __halves2bfloat162(l2, l3);
                } else {
                    *(float4*)(Cout + (size_t)m * Ntot + n_base + q * 4) = v;
                }
            }
        }
        __syncthreads();
    }
    if (wid == 0) TCGEN05_DEALLOC(tmem, 256);
#endif
}

// ---------------------------------------------------------------------------
// Causal flash attention, 512 threads, no-rescale softmax, persistent TMEM
// accumulator. ROUND-14 change: QK(kt+1) issued BEFORE LDTM/exp of S(kt),
// so the tensor pipe runs under the softmax chain.
// ---------------------------------------------------------------------------
#define FLT  512
#define FL_Q    1024
#define FL_K    (FL_Q + 65536)
#define FL_V    (FL_K + 65536)
#define FL_P    (FL_V + 65536)
#define FL_RED  (FL_P + 32768)
#define FL_SMEM (FL_RED + 2048)
#define FIDESC_QK ((1u<<4) | (1u<<7) | (1u<<10) | (8u<<17)  | (8u<<24))   // N=64
#define FIDESC_PV ((1u<<4) | (1u<<7) | (1u<<10) | (16u<<17) | (8u<<24))   // N=128

#if HAS_TC
__device__ __forceinline__ void flash_fill_k(
    uint32_t su, const __nv_bfloat16* Kh, const __nv_bfloat16* Kl,
    int kt, int buf, int tid)
{
    uint32_t base = su + FL_K + buf * 32768;
#pragma unroll
    for (int it = 0; it < 2; it++) {
        int vec = tid + it * FLT;
        int r = vec >> 4;
        int dc = (vec >> 3) & 1;
        int i = vec & 7;
        uint32_t off = dc * 8192 + SMEM_SWIZZLE_128B((uint32_t)(r * 128 + i * 16));
        size_t src = ((size_t)kt * 64 + r) * HDD + dc * 64 + i * 8;
        CP_ASYNC16(base + off,         Kh + src);
        CP_ASYNC16(base + 16384 + off, Kl + src);
    }
    CP_COMMIT();
}
__device__ __forceinline__ void flash_fill_v(
    uint32_t su, const __nv_bfloat16* Vh, const __nv_bfloat16* Vl,
    int kt, int buf, int tid)
{
    uint32_t base = su + FL_V + buf * 32768;
#pragma unroll
    for (int it = 0; it < 2; it++) {
        int vec = tid + it * FLT;
        int d = vec >> 3;
        int i = vec & 7;
        uint32_t off = SMEM_SWIZZLE_128B((uint32_t)(d * 128 + i * 16));
        size_t src = (size_t)d * SS + kt * 64 + i * 8;
        CP_ASYNC16(base + off,         Vh + src);
        CP_ASYNC16(base + 16384 + off, Vl + src);
    }
    CP_COMMIT();
}
__device__ __forceinline__ void flash_issue_qk(uint32_t su, uint32_t tmem,
                                               uint32_t scol, int kbuf)
{
    bool first = true;
#pragma unroll
    for (int p = 0; p < 3; p++) {
        uint32_t ab = su + FL_Q + ((p == 2) ? 32768 : 0);
        uint32_t bb2 = su + FL_K + kbuf * 32768 + ((p == 1) ? 16384 : 0);
#pragma unroll
        for (int dc = 0; dc < 2; dc++) {
            uint64_t a = MAKE_SMEM_DESC(ab + dc * 16384);
            uint64_t b = MAKE_SMEM_DESC(bb2 + dc * 8192);
#pragma unroll
            for (int st = 0; st < 4; st++) {
                mma_ss_f16(tmem + scol, a + st * 2, b + st * 2, FIDESC_QK, !first);
                first = false;
            }
        }
    }
    TCGEN05_COMMIT(su + 16);
}
#endif

__global__ __launch_bounds__(FLT)
void flash_tc_kernel()
{
#if HAS_TC
    extern __shared__ char sm[];
    const uint32_t su = smem_to_u32(sm);
    const int tid = threadIdx.x;
    const int wid = tid >> 5;
    const int lane = tid & 31;
    const int q4 = wid >> 2;
    const int row = (wid & 3) * 32 + lane;
    const int qt = gridDim.x - 1 - blockIdx.x;
    const int bh = blockIdx.y;

    const size_t hoff = (size_t)bh * SS * HDD;
    const __nv_bfloat16 *Qh = gq_h + hoff, *Ql = gq_l + hoff;
    const __nv_bfloat16 *Kh = gk_h + hoff, *Kl = gk_l + hoff;
    const __nv_bfloat16 *Vh = gv_h + hoff, *Vl = gv_l + hoff;

    if (tid == 0) { MBARRIER_INIT(su + 16, 1); MBARRIER_INIT(su + 24, 1); }
    if (wid == 0) { TCGEN05_ALLOC(su + 0, 256); TCGEN05_RELINQUISH(); }
    __syncthreads();
    uint32_t tmem;
    asm volatile("ld.shared.b32 %0, [%1];" : "=r"(tmem) : "r"(su + 0));

    const int KT = 2 * qt + 2;

    // Prologue fills: Q, K0, V0, K1, V1
#pragma unroll
    for (int it = 0; it < 4; it++) {
        int vec = tid + it * FLT;
        int r = vec >> 4;
        int dc = (vec >> 3) & 1;
        int i = vec & 7;
        uint32_t off = dc * 16384 + SMEM_SWIZZLE_128B((uint32_t)(r * 128 + i * 16));
        size_t src = ((size_t)qt * 128 + r) * HDD + dc * 64 + i * 8;
        CP_ASYNC16(su + FL_Q + off,         Qh + src);
        CP_ASYNC16(su + FL_Q + 32768 + off, Ql + src);
    }
    CP_COMMIT();
    flash_fill_k(su, Kh, Kl, 0, 0, tid);
    flash_fill_v(su, Vh, Vl, 0, 0, tid);
    flash_fill_k(su, Kh, Kl, 1 < KT ? 1 : 0, 1, tid);
    flash_fill_v(su, Vh, Vl, 1 < KT ? 1 : 0, 1, tid);

    CP_WAIT_GROUP(2);
    FENCE_PROXY_ASYNC();
    __syncthreads();
    TCGEN05_FENCE_AFTER();
    if (wid == 0 && elect_one_pred()) flash_issue_qk(su, tmem, 0, 0);

    float l_i = 0.0f;
    float* reds = (float*)(sm + FL_RED);
    const int grow = qt * 128 + row;

    for (int kt = 0; kt < KT; kt++) {
        // 1. QK(kt) done: S[kt&1] ready, K[kt&1] free
        MBARRIER_WAIT_PARITY(su + 16, kt & 1);
        TCGEN05_FENCE_AFTER();

        // 2. refill K[kt&1] with K(kt+2)
        {
            int kf = kt + 2 < KT ? kt + 2 : KT - 1;
            flash_fill_k(su, Kh, Kl, kf, kt & 1, tid);
        }

        // 3. K(kt+1)/V(kt) fills (a full iteration old) landed
        CP_WAIT_GROUP(1);
        FENCE_PROXY_ASYNC();
        __syncthreads();
        TCGEN05_FENCE_AFTER();

        // 4. issue QK(kt+1) FIRST — tensor runs under the LDTM/exp below.
        //    S buffer (kt+1)&1's last reader (LDTM at kt-1) is sealed by
        //    FENCE_BEFORE + the barrier above.
        if (kt + 1 < KT && wid == 0 && elect_one_pred())
            flash_issue_qk(su, tmem, (uint32_t)(((kt + 1) & 1) * 64), (kt + 1) & 1);

        // 5. LDTM S(kt); P = exp(s) (masked -> 0); accumulate row sum
        const uint32_t scol = (uint32_t)((kt & 1) * 64);
        uint32_t sreg[16];
        TCGEN05_LD_X16(sreg, tmem + scol + q4 * 16);
        TCGEN05_WAIT_LD();

        const int gc0 = kt * 64 + q4 * 16;
        float sv[16];
        float ps = 0.0f;
#pragma unroll
        for (int c = 0; c < 16; c++) {
            float s = __uint_as_float(sreg[c]);
            float p = (gc0 + c > grow) ? 0.0f : __expf(s);
            sv[c] = p;
            ps += p;
        }
        l_i += ps;
        TCGEN05_FENCE_BEFORE();

        // 6. wait PV(kt-1) (P + V[(kt+1)&1] free), refill V
        if (kt >= 1) {
            MBARRIER_WAIT_PARITY(su + 24, (kt - 1) & 1);
            int vf = kt + 1 < KT ? kt + 1 : KT - 1;
            flash_fill_v(su, Vh, Vl, vf, (kt + 1) & 1, tid);
        }

        // 7. P -> smem bf16 hi/lo
#pragma unroll
        for (int i = 0; i < 2; i++) {
            uint32_t wh[4], wl[4];
#pragma unroll
            for (int g = 0; g < 4; g++) {
                __nv_bfloat16 h0, l0, h1, l1;
                bf16_split(sv[i * 8 + g * 2 + 0], h0, l0);
                bf16_split(sv[i * 8 + g * 2 + 1], h1, l1);
                __nv_bfloat162 ph = __halves2bfloat162(h0, h1);
                __nv_bfloat162 pl = __halves2bfloat162(l0, l1);
                wh[g] = *(uint32_t*)&ph;
                wl[g] = *(uint32_t*)&pl;
            }
            uint32_t off = SMEM_SWIZZLE_128B((uint32_t)(row * 128 + q4 * 32 + i * 16));
            asm volatile("st.shared.v4.b32 [%0], {%1,%2,%3,%4};"
                :: "r"(su + FL_P + off), "r"(wh[0]), "r"(wh[1]), "r"(wh[2]), "r"(wh[3]) : "memory");
            asm volatile("st.shared.v4.b32 [%0], {%1,%2,%3,%4};"
                :: "r"(su + FL_P + 16384 + off), "r"(wl[0]), "r"(wl[1]), "r"(wl[2]), "r"(wl[3]) : "memory");
        }
        FENCE_PROXY_ASYNC();
        __syncthreads();
        TCGEN05_FENCE_AFTER();

        // 8. issue PV(kt) into persistent D
        if (wid == 0) {
            if (elect_one_pred()) {
                uint32_t vbase = su + FL_V + (kt & 1) * 32768;
                bool first = (kt == 0);
#pragma unroll
                for (int p = 0; p < 3; p++) {
                    uint64_t a = MAKE_SMEM_DESC(su + FL_P + ((p == 2) ? 16384 : 0));
                    uint64_t b = MAKE_SMEM_DESC(vbase + ((p == 1) ? 16384 : 0));
#pragma unroll
                    for (int st = 0; st < 4; st++) {
                        mma_ss_f16(tmem + 128, a + st * 2, b + st * 2, FIDESC_PV, !first);
                        first = false;
                    }
                }
                TCGEN05_COMMIT(su + 24);
            }
        }
    }

    // Epilogue
    MBARRIER_WAIT_PARITY(su + 24, (KT - 1) & 1);
    TCGEN05_FENCE_AFTER();
    reds[q4 * 128 + row] = l_i;
    __syncthreads();
    float l = 0.0f;
#pragma unroll
    for (int j = 0; j < 4; j++) l += reds[j * 128 + row];
    const float inv = 1.0f / l;

    float O[32];
    {
        uint32_t dreg[32];
        TCGEN05_LD_X32(dreg, tmem + 128 + q4 * 32);
        TCGEN05_WAIT_LD();
#pragma unroll
        for (int j = 0; j < 32; j++) O[j] = __uint_as_float(dreg[j]);
    }
    CP_WAIT_GROUP(0);

    const int b = bh >> 4, h = bh & 15;
    const int s = qt * 128 + row;
    size_t base = ((size_t)b * SS + s) * HH + h * HDD + q4 * 32;
    __nv_bfloat162* dh = (__nv_bfloat162*)(g_ch + base);
    __nv_bfloat162* dl = (__nv_bfloat162*)(g_cl + base);
#pragma unroll
    for (int i = 0; i < 16; i++) {
        __nv_bfloat16 h0, l0, h1, l1;
        bf16_split(O[i * 2 + 0] * inv, h0, l0);
        bf16_split(O[i * 2 + 1] * inv, h1, l1);
        dh[i] = __halves2bfloat162(h0, h1);
        dl[i] = __halves2bfloat162(l0, l1);
    }
    TCGEN05_FENCE_BEFORE();
    __syncthreads();
    if (wid == 0) TCGEN05_DEALLOC(tmem, 256);
#endif
}

// ---------------------------------------------------------------------------
// Launch sequence
// ---------------------------------------------------------------------------
extern "C" void kernel_launch(void* const* d_in, const int* in_sizes, int n_in,
                              void* d_out, int out_size)
{
    (void)in_sizes; (void)n_in; (void)out_size;
    const float* x     = (const float*)d_in[0];
    const float* w_qkv = (const float*)d_in[2];
    const float* b_qkv = (const float*)d_in[3];
    const float* w_out = (const float*)d_in[4];
    const float* b_out = (const float*)d_in[5];
    float* out = (float*)d_out;

    cudaFuncSetAttribute(mma_gemm_kernel<0>,
        cudaFuncAttributeMaxDynamicSharedMemorySize, GEMM_SMEM);
    cudaFuncSetAttribute(mma_gemm_kernel<1>,
        cudaFuncAttributeMaxDynamicSharedMemorySize, GEMM_SMEM);
    cudaFuncSetAttribute(flash_tc_kernel,
        cudaFuncAttributeMaxDynamicSharedMemorySize, FL_SMEM);

    // 1) Split fp32 operands into bf16 hi/lo (single launch)
    split_all_kernel<<<24576, 256>>>(x, w_qkv, w_out);

    // 2) QKV projection (round-12 GEMM: 2-stage, 2 CTAs/SM)
    {
        dim3 grid(6144 / GBN, 4096 / GBM);
        mma_gemm_kernel<0><<<grid, 256, GEMM_SMEM>>>(b_qkv, nullptr, 2048, 6144);
    }

    // 3) Causal flash attention (512 threads, early-QK reorder)
    {
        dim3 grid(SS / 128, BB * NHH);
        flash_tc_kernel<<<grid, FLT, FL_SMEM>>>();
    }

    // 4) Output projection
    {
        dim3 grid(2048 / GBN, 4096 / GBM);
        mma_gemm_kernel<1><<<grid, 256, GEMM_SMEM>>>(b_out, out, 2048, 2048);
    }
}

// round 17
// speedup vs baseline: 1.0723x; 1.0198x over previous
#include <cuda_runtime.h>
#include <cuda_bf16.h>
#include <cuda_fp16.h>
#include <cstdint>
#include <math.h>

// Problem constants
#define BB   2
#define SS   2048
#define HH   2048
#define NHH  16
#define HDD  128
#define SCALE 0.08838834764831845f   // 1/sqrt(128)

#if defined(__CUDA_ARCH__) && defined(__CUDA_ARCH_FEAT_SM103_ALL)
#define HAS_TC 1
#else
#define HAS_TC 0
#endif

// ---------------------------------------------------------------------------
// Scratch (device globals)
// ---------------------------------------------------------------------------
__device__ __nv_bfloat16 gq_h[8388608], gq_l[8388608];
__device__ __nv_bfloat16 gk_h[8388608], gk_l[8388608];
__device__ __half        gv_h[8388608], gv_l[8388608];   // V stored fp16 hi/lo

__device__ __nv_bfloat16 g_xh[8388608],   g_xl[8388608];
__device__ __nv_bfloat16 g_wqh[12582912], g_wql[12582912];
__device__ __nv_bfloat16 g_ch[8388608],   g_cl[8388608];
__device__ __nv_bfloat16 g_wo[4194304],   g_wol[4194304];

// ---------------------------------------------------------------------------
// PTX helpers
// ---------------------------------------------------------------------------
__device__ __forceinline__ uint32_t smem_to_u32(const void* p) {
    uint32_t a;
    asm("{ .reg .u64 t; cvta.to.shared.u64 t, %1; cvt.u32.u64 %0, t; }"
        : "=r"(a) : "l"(p));
    return a;
}
__device__ __forceinline__ uint32_t elect_one_pred() {
    uint32_t pred;
    asm volatile("{\n\t.reg .pred p;\n\telect.sync _|p, 0xFFFFFFFF;\n\t"
                 "selp.b32 %0, 1, 0, p;\n\t}" : "=r"(pred));
    return pred;
}
#define MBARRIER_INIT(addr, cnt) \
    asm volatile("mbarrier.init.shared.b64 [%0], %1;" :: "r"((uint32_t)(addr)), "r"((uint32_t)(cnt)) : "memory")
#define MBARRIER_WAIT_PARITY(addr, par) do {                                   \
    uint32_t _m = (uint32_t)(addr); uint32_t _p = (uint32_t)(par); uint32_t _d;\
    asm volatile("{\n\t.reg .pred p;\n\t"                                      \
        "mbarrier.try_wait.parity.acquire.cta.shared::cta.b64 p, [%1], %2;\n\t"\
        "selp.b32 %0, 1, 0, p;\n\t}" : "=r"(_d) : "r"(_m), "r"(_p) : "memory");\
    if (!_d) {                                                                 \
        asm volatile("{\n\t.reg .pred P1;\n\t"                                 \
        "WL_%=:\n\t"                                                           \
        "mbarrier.try_wait.parity.acquire.cta.shared::cta.b64 P1, [%0], %1, 0x989680;\n\t" \
        "@P1 bra.uni WD_%=;\n\tbra.uni WL_%=;\n\tWD_%=:\n\t}"                  \
        :: "r"(_m), "r"(_p) : "memory");                                       \
    }                                                                          \
} while (0)
#define TCGEN05_ALLOC(saddr, ncols) \
    asm volatile("tcgen05.alloc.cta_group::1.sync.aligned.shared::cta.b32 [%0], %1;" \
                 :: "r"((uint32_t)(saddr)), "r"((uint32_t)(ncols)) : "memory")
#define TCGEN05_DEALLOC(taddr, ncols) \
    asm volatile("tcgen05.dealloc.cta_group::1.sync.aligned.b32 %0, %1;" :: "r"(taddr), "r"((uint32_t)(ncols)))
#define TCGEN05_RELINQUISH() \
    asm volatile("tcgen05.relinquish_alloc_permit.cta_group::1.sync.aligned;")
#define TCGEN05_COMMIT(mbar) \
    asm volatile("tcgen05.commit.cta_group::1.mbarrier::arrive::one.shared::cluster.b64 [%0];" \
                 :: "r"((uint32_t)(mbar)) : "memory")
#define TCGEN05_WAIT_LD() asm volatile("tcgen05.wait::ld.sync.aligned;" ::: "memory")
#define TCGEN05_FENCE_BEFORE() asm volatile("tcgen05.fence::before_thread_sync;" ::: "memory")
#define TCGEN05_FENCE_AFTER()  asm volatile("tcgen05.fence::after_thread_sync;" ::: "memory")
#define FENCE_PROXY_ASYNC() asm volatile("fence.proxy.async.shared::cta;" ::: "memory")
#define CP_ASYNC16(dst, src) \
    asm volatile("cp.async.cg.shared.global [%0], [%1], 16;" :: "r"((uint32_t)(dst)), "l"(src) : "memory")
#define CP_COMMIT() asm volatile("cp.async.commit_group;" ::: "memory")
#define CP_WAIT_GROUP(n) asm volatile("cp.async.wait_group %0;" :: "n"(n) : "memory")
#define TCGEN05_LD_X32(r, taddr)                                               \
    asm volatile("tcgen05.ld.sync.aligned.32x32b.x32.b32 "                     \
        "{%0, %1, %2, %3, %4, %5, %6, %7, "                                    \
        " %8, %9, %10, %11, %12, %13, %14, %15, "                              \
        " %16, %17, %18, %19, %20, %21, %22, %23, "                            \
        " %24, %25, %26, %27, %28, %29, %30, %31}, [%32];"                     \
        : "=r"((r)[0]), "=r"((r)[1]), "=r"((r)[2]), "=r"((r)[3]),              \
          "=r"((r)[4]), "=r"((r)[5]), "=r"((r)[6]), "=r"((r)[7]),              \
          "=r"((r)[8]), "=r"((r)[9]), "=r"((r)[10]), "=r"((r)[11]),            \
          "=r"((r)[12]), "=r"((r)[13]), "=r"((r)[14]), "=r"((r)[15]),          \
          "=r"((r)[16]), "=r"((r)[17]), "=r"((r)[18]), "=r"((r)[19]),          \
          "=r"((r)[20]), "=r"((r)[21]), "=r"((r)[22]), "=r"((r)[23]),          \
          "=r"((r)[24]), "=r"((r)[25]), "=r"((r)[26]), "=r"((r)[27]),          \
          "=r"((r)[28]), "=r"((r)[29]), "=r"((r)[30]), "=r"((r)[31])           \
        : "r"(taddr))

#define SMEM_SWIZZLE_128B(b) ((b) ^ (((b) >> 3) & 0x70))
static constexpr uint64_t SMEM_DESC_BASE_SW128 =
    (uint64_t(2) << 61) | (uint64_t(1) << 46) | (uint64_t(64) << 32) | (uint64_t(1) << 16);
#define MAKE_SMEM_DESC(a) (SMEM_DESC_BASE_SW128 | ((uint64_t)((a) >> 4) & 0x3FFF))

#if HAS_TC
__device__ __forceinline__ void mma_ss_f16(uint32_t d, uint64_t a, uint64_t b,
                                           uint32_t idesc, bool acc) {
    uint32_t e = acc ? 1u : 0u;
    asm volatile(
        "{\n\t.reg .pred p;\n\t"
        "setp.ne.u32 p, %5, 0;\n\t"
        "tcgen05.mma.cta_group::1.kind::f16 [%0], %1, %2, %3, {%4, %4, %4, %4}, p;\n\t}"
        :: "r"(d), "l"(a), "l"(b), "r"(idesc), "r"(0u), "r"(e) : "memory");
}
#endif

__device__ __forceinline__ void bf16_split(float v, __nv_bfloat16& h, __nv_bfloat16& l) {
    h = __float2bfloat16_rn(v);
    l = __float2bfloat16_rn(v - __bfloat162float(h));
}
__device__ __forceinline__ void fp16_split(float v, __half& h, __half& l) {
    h = __float2half_rn(v);
    l = __float2half_rn(v - __half2float(h));
}

// ---------------------------------------------------------------------------
// Merged split kernel (round-12 passing version)
// ---------------------------------------------------------------------------
__global__ __launch_bounds__(256)
void split_all_kernel(const float* __restrict__ x,
                      const float* __restrict__ wq,
                      const float* __restrict__ wo)
{
    int bid = blockIdx.x;
    const float* s;
    __nv_bfloat16 *hi, *lo;
    int base;
    if (bid < 8192)        { s = x;  hi = g_xh;  lo = g_xl;  base = bid; }
    else if (bid < 20480)  { s = wq; hi = g_wqh; lo = g_wql; base = bid - 8192; }
    else                   { s = wo; hi = g_wo;  lo = g_wol; base = bid - 20480; }

    int i = (base * 256 + threadIdx.x) * 4;
    float4 v = *(const float4*)(s + i);
    __nv_bfloat16 h0, h1, h2, h3, l0, l1, l2, l3;
    bf16_split(v.x, h0, l0); bf16_split(v.y, h1, l1);
    bf16_split(v.z, h2, l2); bf16_split(v.w, h3, l3);
    __nv_bfloat162* H = (__nv_bfloat162*)(hi + i);
    __nv_bfloat162* L = (__nv_bfloat162*)(lo + i);
    H[0] = __halves2bfloat162(h0, h1); H[1] = __halves2bfloat162(h2, h3);
    L[0] = __halves2bfloat162(l0, l1); L[1] = __halves2bfloat162(l2, l3);
}

// ---------------------------------------------------------------------------
// tcgen05 bf16x3 GEMM — round-12 version; MODE 0 v-epilogue now fp16 split.
// ---------------------------------------------------------------------------
#define GBM 128
#define GBN 256
#define GBK 32
#define STAGE_BYTES 49152
#define GEMM_SMEM   (1024 + 2 * STAGE_BYTES)   // 99,328
#define GIDESC ((1u<<4) | (1u<<7) | (1u<<10) | ((GBN/8u)<<17) | ((GBM/16u)<<24))

#if HAS_TC
__device__ __forceinline__ void fill_stage_async(
    uint32_t su, int st,
    const __nv_bfloat16* __restrict__ Ah, const __nv_bfloat16* __restrict__ Al,
    const __nv_bfloat16* __restrict__ Bh, const __nv_bfloat16* __restrict__ Bl,
    int m0, int n0, int k0, int K, int tid)
{
    uint32_t stage = su + 1024 + st * STAGE_BYTES;
#pragma unroll
    for (int i = 0; i < 4; i++) {                 // A: 128 rows
        int q = tid + i * 256;
        int r = q >> 3, c = q & 7;
        uint32_t off = SMEM_SWIZZLE_128B((uint32_t)(r * 128 + c * 16));
        const __nv_bfloat16* srcp = (c < 4)
            ? Ah + (size_t)(m0 + r) * K + k0 + c * 8
            : Al + (size_t)(m0 + r) * K + k0 + (c - 4) * 8;
        CP_ASYNC16(stage + off, srcp);
    }
#pragma unroll
    for (int i = 0; i < 8; i++) {                 // B: 256 rows
        int q = tid + i * 256;
        int r = q >> 3, c = q & 7;
        uint32_t off = SMEM_SWIZZLE_128B((uint32_t)(r * 128 + c * 16));
        const __nv_bfloat16* srcp = (c < 4)
            ? Bh + (size_t)(n0 + r) * K + k0 + c * 8
            : Bl + (size_t)(n0 + r) * K + k0 + (c - 4) * 8;
        CP_ASYNC16(stage + 16384 + off, srcp);
    }
    CP_COMMIT();
}
#endif

template <int MODE>
__global__ __launch_bounds__(256, 2)
void mma_gemm_kernel(const float* __restrict__ bias,
                     float* __restrict__ Cout,
                     int K, int Ntot)
{
#if HAS_TC
    extern __shared__ char sm[];
    const uint32_t su = smem_to_u32(sm);
    const int tid = threadIdx.x;
    const int wid = tid >> 5;
    const int lane = tid & 31;
    const int m0 = blockIdx.y * GBM;
    const int n0 = blockIdx.x * GBN;

    const __nv_bfloat16* Ah = (MODE == 0) ? g_xh  : g_ch;
    const __nv_bfloat16* Al = (MODE == 0) ? g_xl  : g_cl;
    const __nv_bfloat16* Bh = (MODE == 0) ? g_wqh : g_wo;
    const __nv_bfloat16* Bl = (MODE == 0) ? g_wql : g_wol;

    if (tid == 0) { MBARRIER_INIT(su + 0, 1); MBARRIER_INIT(su + 8, 1); }
    if (wid == 0) { TCGEN05_ALLOC(su + 32, 256); TCGEN05_RELINQUISH(); }
    __syncthreads();
    uint32_t tmem;
    asm volatile("ld.shared.b32 %0, [%1];" : "=r"(tmem) : "r"(su + 32));

    const int NC = K / GBK;   // 64
    fill_stage_async(su, 0, Ah, Al, Bh, Bl, m0, n0, 0 * GBK, K, tid);
    fill_stage_async(su, 1, Ah, Al, Bh, Bl, m0, n0, 1 * GBK, K, tid);

    for (int c = 0; c < NC; c++) {
        const int st = c & 1;
        if (c < NC - 1) CP_WAIT_GROUP(1);
        else            CP_WAIT_GROUP(0);
        FENCE_PROXY_ASYNC();
        __syncthreads();

        if (wid == 0) {
            if (elect_one_pred()) {
                uint32_t sb = su + 1024 + st * STAGE_BYTES;
                uint64_t dA = MAKE_SMEM_DESC(sb);
                uint64_t dB = MAKE_SMEM_DESC(sb + 16384);
                mma_ss_f16(tmem, dA + 0, dB + 0, GIDESC, c != 0);
                mma_ss_f16(tmem, dA + 2, dB + 2, GIDESC, true);
                mma_ss_f16(tmem, dA + 0, dB + 4, GIDESC, true);
                mma_ss_f16(tmem, dA + 2, dB + 6, GIDESC, true);
                mma_ss_f16(tmem, dA + 4, dB + 0, GIDESC, true);
                mma_ss_f16(tmem, dA + 6, dB + 2, GIDESC, true);
                TCGEN05_COMMIT(su + st * 8);
            }
        }
        if (c + 2 < NC) {
            MBARRIER_WAIT_PARITY(su + st * 8, (c >> 1) & 1);
            fill_stage_async(su, st, Ah, Al, Bh, Bl, m0, n0, (c + 2) * GBK, K, tid);
        }
    }
    MBARRIER_WAIT_PARITY(su + ((NC - 1) & 1) * 8, ((NC - 1) >> 1) & 1);
    TCGEN05_FENCE_AFTER();
    __syncthreads();

    float* ep = (float*)(sm + 1024);
    for (int c0 = 0; c0 < GBN; c0 += 32) {
        if (wid < 4) {
            uint32_t regs[32];
            TCGEN05_LD_X32(regs, tmem + c0);
            TCGEN05_WAIT_LD();
            int r = wid * 32 + lane;
#pragma unroll
            for (int c = 0; c < 32; c++) ep[r * 33 + c] = __uint_as_float(regs[c]);
        }
        __syncthreads();
        const int n_base = n0 + c0;
        const int which = n_base >> 11;

        if (MODE == 0 && which == 2) {
            // v: head-transposed FP16 hi/lo, coalesced along s
            int rest = n_base & 2047;
            int h = rest >> 7, dbase = rest & 127;
            size_t head = (size_t)((m0 >> 11) * NHH + h);
            int s0 = m0 & 2047;
#pragma unroll
            for (int k4 = 0; k4 < 4; k4++) {
                int col = wid * 4 + k4;
                float bval = bias[n_base + col];
                __half* dh = gv_h + (head * HDD + dbase + col) * SS + s0;
                __half* dl = gv_l + (head * HDD + dbase + col) * SS + s0;
#pragma unroll
                for (int j = 0; j < 4; j++) {
                    int r = lane + j * 32;
                    float val = ep[r * 33 + col] + bval;
                    __half hh, ll;
                    fp16_split(val, hh, ll);
                    dh[r] = hh; dl[r] = ll;
                }
            }
        } else {
#pragma unroll
            for (int i = 0; i < 4; i++) {
                int idx = tid + i * 256;
                int r = idx >> 3, q = idx & 7;
                float4 v;
                v.x = ep[r * 33 + q * 4 + 0] + bias[n_base + q * 4 + 0];
                v.y = ep[r * 33 + q * 4 + 1] + bias[n_base + q * 4 + 1];
                v.z = ep[r * 33 + q * 4 + 2] + bias[n_base + q * 4 + 2];
                v.w = ep[r * 33 + q * 4 + 3] + bias[n_base + q * 4 + 3];
                int m = m0 + r;
                if (MODE == 0) {
                    int bb = m >> 11, s = m & 2047;
                    int rest = n_base & 2047;
                    int h = rest >> 7;
                    int d = (rest & 127) + q * 4;
                    size_t off = (((size_t)(bb * NHH + h)) * SS + s) * HDD + d;
                    if (which == 0) { v.x *= SCALE; v.y *= SCALE; v.z *= SCALE; v.w *= SCALE; }
                    __nv_bfloat16 h0, h1, h2, h3, l0, l1, l2, l3;
                    bf16_split(v.x, h0, l0); bf16_split(v.y, h1, l1);
                    bf16_split(v.z, h2, l2); bf16_split(v.w, h3, l3);
                    __nv_bfloat16* dh = (which == 0) ? gq_h : gk_h;
                    __nv_bfloat16* dl = (which == 0) ? gq_l : gk_l;
                    ((__nv_bfloat162*)(dh + off))[0] = __halves2bfloat162(h0, h1);
                    ((__nv_bfloat162*)(dh + off))[1] = __halves2bfloat162(h2, h3);
                    ((__nv_bfloat162*)(dl + off))[0] = __halves2bfloat162(l0, l1);
                    ((__nv_bfloat162*)(dl + off))[1] = __halves2bfloat162(l2, l3);
                } else {
                    *(float4*)(Cout + (size_t)m * Ntot + n_base + q * 4) = v;
                }
            }
        }
        __syncthreads();
    }
    if (wid == 0) TCGEN05_DEALLOC(tmem, 256);
#endif
}

// ---------------------------------------------------------------------------
// Causal flash attention, kv-tile = 128, 512 threads, no-rescale softmax,
// persistent TMEM accumulator D. P and V both FP16 -> PV is uniform fp16
// kind::f16 MMA (atype=btype=0; the round-16 mixed-dtype form traps).
// ---------------------------------------------------------------------------
#define FLT  512
#define FL_Q    1024                     // hi c0,c1 @0,16384; lo @32768+
#define FL_K    (FL_Q + 65536)
#define FL_V    (FL_K + 65536)
#define FL_P    (FL_V + 65536)           // single fp16, c0,c1 (16K each)
#define FL_RED  (FL_P + 32768)
#define FL_SMEM (FL_RED + 2048)          // 232,448 = 227 KB exactly
#define FIDESC_QK ((1u<<4) | (1u<<7) | (1u<<10) | (16u<<17) | (8u<<24))  // bf16 x bf16
#define FIDESC_PV ((1u<<4) | (0u<<7) | (0u<<10) | (16u<<17) | (8u<<24))  // fp16 x fp16

#if HAS_TC
__device__ __forceinline__ void flash_fill_k128(
    uint32_t su, const __nv_bfloat16* Kh, const __nv_bfloat16* Kl,
    int kt, int tid)
{
#pragma unroll
    for (int it = 0; it < 4; it++) {
        int vec = tid + it * FLT;            // 0..2047
        int dc = vec >> 10;
        int rem = vec & 1023;
        int r = rem >> 3;
        int i = rem & 7;
        uint32_t off = dc * 16384 + SMEM_SWIZZLE_128B((uint32_t)(r * 128 + i * 16));
        size_t src = ((size_t)kt * 128 + r) * HDD + dc * 64 + i * 8;
        CP_ASYNC16(su + FL_K + off,         Kh + src);
        CP_ASYNC16(su + FL_K + 32768 + off, Kl + src);
    }
    CP_COMMIT();
}
__device__ __forceinline__ void flash_fill_v128(
    uint32_t su, const __half* Vh, const __half* Vl,
    int kt, int tid)
{
#pragma unroll
    for (int it = 0; it < 4; it++) {
        int vec = tid + it * FLT;            // 0..2047
        int c = vec >> 10;
        int rem = vec & 1023;
        int d = rem >> 3;
        int i = rem & 7;
        uint32_t off = c * 16384 + SMEM_SWIZZLE_128B((uint32_t)(d * 128 + i * 16));
        size_t src = (size_t)d * SS + kt * 128 + c * 64 + i * 8;
        CP_ASYNC16(su + FL_V + off,         Vh + src);
        CP_ASYNC16(su + FL_V + 32768 + off, Vl + src);
    }
    CP_COMMIT();
}
__device__ __forceinline__ void flash_issue_qk128(uint32_t su, uint32_t tmem,
                                                  uint32_t scol)
{
    bool first = true;
#pragma unroll
    for (int p = 0; p < 3; p++) {
        uint32_t ab = su + FL_Q + ((p == 2) ? 32768 : 0);
        uint32_t bb = su + FL_K + ((p == 1) ? 32768 : 0);
#pragma unroll
        for (int dc = 0; dc < 2; dc++) {
            uint64_t a = MAKE_SMEM_DESC(ab + dc * 16384);
            uint64_t b = MAKE_SMEM_DESC(bb + dc * 16384);
#pragma unroll
            for (int st = 0; st < 4; st++) {
                mma_ss_f16(tmem + scol, a + st * 2, b + st * 2, FIDESC_QK, !first);
                first = false;
            }
        }
    }
    TCGEN05_COMMIT(su + 16);
}
#endif

__global__ __launch_bounds__(FLT)
void flash_tc_kernel()
{
#if HAS_TC
    extern __shared__ char sm[];
    const uint32_t su = smem_to_u32(sm);
    const int tid = threadIdx.x;
    const int wid = tid >> 5;
    const int lane = tid & 31;
    const int q4 = wid >> 2;
    const int row = (wid & 3) * 32 + lane;
    const int qt = gridDim.x - 1 - blockIdx.x;
    const int bh = blockIdx.y;

    const size_t hoff = (size_t)bh * SS * HDD;
    const __nv_bfloat16 *Qh = gq_h + hoff, *Ql = gq_l + hoff;
    const __nv_bfloat16 *Kh = gk_h + hoff, *Kl = gk_l + hoff;
    const __half *Vh = gv_h + hoff, *Vl = gv_l + hoff;

    if (tid == 0) { MBARRIER_INIT(su + 16, 1); MBARRIER_INIT(su + 24, 1); }
    if (wid == 0) { TCGEN05_ALLOC(su + 0, 512); TCGEN05_RELINQUISH(); }
    __syncthreads();
    uint32_t tmem;
    asm volatile("ld.shared.b32 %0, [%1];" : "=r"(tmem) : "r"(su + 0));

    const int KT = qt + 1;

    // Prologue: fill Q, K0, V0
#pragma unroll
    for (int it = 0; it < 4; it++) {
        int vec = tid + it * FLT;
        int dc = vec >> 10;
        int rem = vec & 1023;
        int r = rem >> 3;
        int i = rem & 7;
        uint32_t off = dc * 16384 + SMEM_SWIZZLE_128B((uint32_t)(r * 128 + i * 16));
        size_t src = ((size_t)qt * 128 + r) * HDD + dc * 64 + i * 8;
        CP_ASYNC16(su + FL_Q + off,         Qh + src);
        CP_ASYNC16(su + FL_Q + 32768 + off, Ql + src);
    }
    CP_COMMIT();
    flash_fill_k128(su, Kh, Kl, 0, tid);
    flash_fill_v128(su, Vh, Vl, 0, tid);

    CP_WAIT_GROUP(0);
    FENCE_PROXY_ASYNC();
    __syncthreads();
    TCGEN05_FENCE_AFTER();
    if (wid == 0 && elect_one_pred()) flash_issue_qk128(su, tmem, 0);

    float l_i = 0.0f;
    float* reds = (float*)(sm + FL_RED);
    const int grow = qt * 128 + row;

    for (int kt = 0; kt < KT; kt++) {
        // 1. QK(kt) done: S[kt&1] ready, K buffer free
        MBARRIER_WAIT_PARITY(su + 16, kt & 1);
        TCGEN05_FENCE_AFTER();

        // 2. fill K(kt+1) (single buffer; flies under LDTM/exp)
        if (kt + 1 < KT) flash_fill_k128(su, Kh, Kl, kt + 1, tid);

        // 3. LDTM S(kt), exp, round to FP16, sum of rounded
        const uint32_t scol = (uint32_t)((kt & 1) * 128);
        uint32_t sreg[32];
        TCGEN05_LD_X32(sreg, tmem + scol + q4 * 32);
        TCGEN05_WAIT_LD();

        const int gc0 = kt * 128 + q4 * 32;
        uint32_t pw[16];                   // 32 fp16 packed
        float ps = 0.0f;
#pragma unroll
        for (int g = 0; g < 16; g++) {
            float s0 = __uint_as_float(sreg[g * 2 + 0]);
            float s1 = __uint_as_float(sreg[g * 2 + 1]);
            float p0 = (gc0 + g * 2 + 0 > grow) ? 0.0f : __expf(s0);
            float p1 = (gc0 + g * 2 + 1 > grow) ? 0.0f : __expf(s1);
            __half b0 = __float2half_rn(p0);
            __half b1 = __float2half_rn(p1);
            ps += __half2float(b0) + __half2float(b1);
            __half2 pr = __halves2half2(b0, b1);
            pw[g] = *(uint32_t*)&pr;
        }
        l_i += ps;
        TCGEN05_FENCE_BEFORE();            // seal S reads before reuse

        // 4. wait PV(kt-1) (P free, V buffer free); fill V(kt)
        if (kt >= 1) {
            MBARRIER_WAIT_PARITY(su + 24, (kt - 1) & 1);
            TCGEN05_FENCE_AFTER();
            flash_fill_v128(su, Vh, Vl, kt, tid);
        }

        // 5. store P (single fp16): this thread's 32 cols of its row
        {
            uint32_t pbase = su + FL_P + (q4 >> 1) * 16384;
            uint32_t rowoff = (uint32_t)(row * 128 + (q4 & 1) * 64);
#pragma unroll
            for (int v = 0; v < 4; v++) {
                uint32_t off = SMEM_SWIZZLE_128B(rowoff + v * 16);
                asm volatile("st.shared.v4.b32 [%0], {%1,%2,%3,%4};"
                    :: "r"(pbase + off), "r"(pw[v * 4 + 0]), "r"(pw[v * 4 + 1]),
                       "r"(pw[v * 4 + 2]), "r"(pw[v * 4 + 3]) : "memory");
            }
        }

        // 6. single barrier: K(kt+1) + V(kt) fills landed, P visible
        FENCE_PROXY_ASYNC();
        CP_WAIT_GROUP(0);
        __syncthreads();
        TCGEN05_FENCE_AFTER();

        // 7. issue QK(kt+1) into other S buffer
        if (kt + 1 < KT && wid == 0 && elect_one_pred())
            flash_issue_qk128(su, tmem, (uint32_t)(((kt + 1) & 1) * 128));

        // 8. issue PV(kt) into persistent D: fp16 P x fp16 V (hi then lo)
        if (wid == 0) {
            if (elect_one_pred()) {
                bool first = (kt == 0);
#pragma unroll
                for (int p = 0; p < 2; p++) {       // vh, vl
                    uint32_t vb = su + FL_V + ((p == 1) ? 32768 : 0);
#pragma unroll
                    for (int c = 0; c < 2; c++) {
                        uint64_t a = MAKE_SMEM_DESC(su + FL_P + c * 16384);
                        uint64_t b = MAKE_SMEM_DESC(vb + c * 16384);
#pragma unroll
                        for (int st = 0; st < 4; st++) {
                            mma_ss_f16(tmem + 256, a + st * 2, b + st * 2,
                                       FIDESC_PV, !first);
                            first = false;
                        }
                    }
                }
                TCGEN05_COMMIT(su + 24);
            }
        }
    }

    // Epilogue
    MBARRIER_WAIT_PARITY(su + 24, (KT - 1) & 1);
    TCGEN05_FENCE_AFTER();
    reds[q4 * 128 + row] = l_i;
    __syncthreads();
    float l = 0.0f;
#pragma unroll
    for (int j = 0; j < 4; j++) l += reds[j * 128 + row];
    const float inv = 1.0f / l;

    float O[32];
    {
        uint32_t dreg[32];
        TCGEN05_LD_X32(dreg, tmem + 256 + q4 * 32);
        TCGEN05_WAIT_LD();
#pragma unroll
        for (int j = 0; j < 32; j++) O[j] = __uint_as_float(dreg[j]);
    }

    const int b = bh >> 4, h = bh & 15;
    const int s = qt * 128 + row;
    size_t base = ((size_t)b * SS + s) * HH + h * HDD + q4 * 32;
    __nv_bfloat162* dh = (__nv_bfloat162*)(g_ch + base);
    __nv_bfloat162* dl = (__nv_bfloat162*)(g_cl + base);
#pragma unroll
    for (int i = 0; i < 16; i++) {
        __nv_bfloat16 h0, l0, h1, l1;
        bf16_split(O[i * 2 + 0] * inv, h0, l0);
        bf16_split(O[i * 2 + 1] * inv, h1, l1);
        dh[i] = __halves2bfloat162(h0, h1);
        dl[i] = __halves2bfloat162(l0, l1);
    }
    TCGEN05_FENCE_BEFORE();
    __syncthreads();
    if (wid == 0) TCGEN05_DEALLOC(tmem, 512);
#endif
}

// ---------------------------------------------------------------------------
// Launch sequence
// ---------------------------------------------------------------------------
extern "C" void kernel_launch(void* const* d_in, const int* in_sizes, int n_in,
                              void* d_out, int out_size)
{
    (void)in_sizes; (void)n_in; (void)out_size;
    const float* x     = (const float*)d_in[0];
    const float* w_qkv = (const float*)d_in[2];
    const float* b_qkv = (const float*)d_in[3];
    const float* w_out = (const float*)d_in[4];
    const float* b_out = (const float*)d_in[5];
    float* out = (float*)d_out;

    cudaFuncSetAttribute(mma_gemm_kernel<0>,
        cudaFuncAttributeMaxDynamicSharedMemorySize, GEMM_SMEM);
    cudaFuncSetAttribute(mma_gemm_kernel<1>,
        cudaFuncAttributeMaxDynamicSharedMemorySize, GEMM_SMEM);
    cudaFuncSetAttribute(flash_tc_kernel,
        cudaFuncAttributeMaxDynamicSharedMemorySize, FL_SMEM);

    // 1) Split fp32 operands into bf16 hi/lo (single launch)
    split_all_kernel<<<24576, 256>>>(x, w_qkv, w_out);

    // 2) QKV projection (round-12 GEMM: 2-stage, 2 CTAs/SM)
    {
        dim3 grid(6144 / GBN, 4096 / GBM);
        mma_gemm_kernel<0><<<grid, 256, GEMM_SMEM>>>(b_qkv, nullptr, 2048, 6144);
    }

    // 3) Causal flash attention (kv-tile 128, fp16 P & V, one sync/iter)
    {
        dim3 grid(SS / 128, BB * NHH);
        flash_tc_kernel<<<grid, FLT, FL_SMEM>>>();
    }

    // 4) Output projection
    {
        dim3 grid(2048 / GBN, 4096 / GBM);
        mma_gemm_kernel<1><<<grid, 256, GEMM_SMEM>>>(b_out, out, 2048, 2048);
    }
}